// round 7
// baseline (speedup 1.0000x reference)
#include <cuda_runtime.h>
#include <cuda_fp16.h>
#include <cstdint>

// Lorenz96 via HMMA, flipped GEMM: M=positions(80), N=channels(40 pad 37), K=240.
// B = W2^T fragments hoisted into registers (tile-invariant, 150 regs).
// Per tile: conv1 fp32 -> hT fp16; A frags ldmatrix'd from hT (im2col folded);
// 15kt x 5nt HMMA; epilogue relu(+b2)*W3 in-thread + quad shfl reduce + stencil.

#define NT     160
#define GRID   296
#define X      40
#define SPT    2
#define NTILES 32768          // 65536 / SPT
#define AST    248            // W2h row stride (halves)
#define HTST   56             // hT row stride (halves)
#define HT_SAMP (44*HTST)     // 2464 halves per sample

// smem byte offsets
#define SM_W2H   0            // 40*248*2 = 19840
#define SM_HT    19840        // 2*2464*2 = 9856
#define SM_US    29696        // 2*44*4 = 352
#define SM_W1    30048        // 1440
#define SM_B1    31488        // 288
#define SM_BW    31776        // 20 float4 = 320
#define SM_COEFF 32096        // 72
#define SM_B3    32168        // 4
#define SM_PART  32192        // 80 f32 = 320
#define SM_TOTAL 32768

__device__ __forceinline__ uint32_t smem_u32(const void* p) {
    uint32_t a;
    asm("{ .reg .u64 t; cvta.to.shared.u64 t, %1; cvt.u32.u64 %0, t; }" : "=r"(a) : "l"(p));
    return a;
}
__device__ __forceinline__ void ldmatrix_x4(uint32_t& a0, uint32_t& a1, uint32_t& a2, uint32_t& a3,
                                            uint32_t addr) {
    asm volatile("ldmatrix.sync.aligned.m8n8.x4.shared.b16 {%0,%1,%2,%3}, [%4];"
                 : "=r"(a0), "=r"(a1), "=r"(a2), "=r"(a3) : "r"(addr));
}
__device__ __forceinline__ void ldmatrix_x2(uint32_t& a0, uint32_t& a1, uint32_t addr) {
    asm volatile("ldmatrix.sync.aligned.m8n8.x2.shared.b16 {%0,%1}, [%2];"
                 : "=r"(a0), "=r"(a1) : "r"(addr));
}
__device__ __forceinline__ void mma16816(float* c, uint32_t a0, uint32_t a1, uint32_t a2, uint32_t a3,
                                         uint32_t b0, uint32_t b1) {
    asm volatile("mma.sync.aligned.m16n8k16.row.col.f32.f16.f16.f32 "
                 "{%0,%1,%2,%3}, {%4,%5,%6,%7}, {%8,%9}, {%0,%1,%2,%3};"
                 : "+f"(c[0]), "+f"(c[1]), "+f"(c[2]), "+f"(c[3])
                 : "r"(a0), "r"(a1), "r"(a2), "r"(a3), "r"(b0), "r"(b1));
}

__global__ __launch_bounds__(NT, 2)
void l96_flip_kernel(const float* __restrict__ u,  const float* __restrict__ coeff,
                     const float* __restrict__ W1, const float* __restrict__ b1,
                     const float* __restrict__ W2, const float* __restrict__ b2,
                     const float* __restrict__ W3, const float* __restrict__ b3,
                     float* __restrict__ out)
{
    extern __shared__ char sm[];
    const uint32_t smb = smem_u32(sm);
    const int tid  = threadIdx.x;
    const int wid  = tid >> 5;
    const int lane = tid & 31;

    float*  W1s  = (float*)(sm + SM_W1);
    float*  b1s  = (float*)(sm + SM_B1);
    float*  usf  = (float*)(sm + SM_US);
    float*  part = (float*)(sm + SM_PART);
    float4* bw   = (float4*)(sm + SM_BW);
    __half* W2h  = (__half*)(sm + SM_W2H);
    __half* hTh  = (__half*)(sm + SM_HT);

    // ---- stage weights ----
    for (int i = tid; i < 4960; i += NT) ((uint32_t*)(sm + SM_W2H))[i] = 0;
    for (int i = tid; i < 360;  i += NT) W1s[i] = W1[i];
    for (int i = tid; i < 72;   i += NT) b1s[i] = b1[i];
    for (int i = tid; i < 18;   i += NT) ((float*)(sm + SM_COEFF))[i] = coeff[i];
    if (tid == 0) ((float*)(sm + SM_B3))[0] = b3[0];
    // packed (b2,b2',w3,w3') table: entry nt*4+q -> channels c=nt*8+2q, c+1
    for (int i = tid; i < 20; i += NT) {
        int c = (i >> 2) * 8 + (i & 3) * 2;
        float bx = (c     < 37) ? b2[c]     : 0.f;
        float by = (c + 1 < 37) ? b2[c + 1] : 0.f;
        float wz = (c     < 37) ? W3[c]     : 0.f;
        float ww = (c + 1 < 37) ? W3[c + 1] : 0.f;
        bw[i] = make_float4(bx, by, wz, ww);
    }
    __syncthreads();
    // W2h[co][k=d*48+ci] = W2[co][ci*5+d], rows 37-39 stay zero
    for (int i = tid; i < 37 * 240; i += NT) {
        int co = i / 240, k = i % 240;
        int d = k / 48, ci = k % 48;
        W2h[co * AST + k] = __float2half(W2[co * 240 + ci * 5 + d]);
    }
    __syncthreads();

    // ---- hoist all B = W2^T fragments into registers (tile-invariant) ----
    uint32_t bf[15][5][2];
    {
        const uint32_t bb = smb + SM_W2H +
            (uint32_t)(((lane & 7) * AST + ((lane >> 3) & 1) * 8) * 2);
        #pragma unroll
        for (int kt = 0; kt < 15; kt++)
            #pragma unroll
            for (int nt = 0; nt < 5; nt++)
                ldmatrix_x2(bf[kt][nt][0], bf[kt][nt][1],
                            bb + (uint32_t)(nt * (8 * AST * 2) + kt * 32));
    }

    // ---- per-lane A (im2col) base address: row = global position ----
    uint32_t a_base;
    {
        int posg = wid * 16 + (lane & 15);
        int s = posg / X, p = posg % X;
        a_base = smb + SM_HT +
            (uint32_t)((s * HT_SAMP + p * HTST + ((lane >> 4) << 3)) * 2);
    }

    // ---- conv1 role: threads 0..143, fixed channel ----
    const int  c1c  = tid % 48;
    const int  sp0  = tid / 48;          // 0..2 for active threads
    const bool c1on = (tid < 144);
    float w1r[5], w1g[5], b1v = 0.f, b1g = 0.f;
    if (c1on) {
        b1v = b1s[c1c];
        #pragma unroll
        for (int d = 0; d < 5; d++) w1r[d] = W1s[c1c * 5 + d];
        if (c1c >= 24) {
            b1g = b1s[(c1c + 24)];
            #pragma unroll
            for (int d = 0; d < 5; d++) w1g[d] = W1s[(c1c + 24) * 5 + d];
        }
    }

    for (int tile = blockIdx.x; tile < NTILES; tile += GRID) {
        const size_t gbase = (size_t)tile * (SPT * X);

        // ---- stage u (2 samples, halo 44) ----
        if (tid < SPT * X) {
            int s = tid / X, p = tid % X;
            float v = u[gbase + tid];
            float* ur = usf + s * 44;
            ur[p + 2] = v;
            if (p < 2)   ur[p + 42] = v;
            if (p >= 38) ur[p - 38] = v;
        }
        __syncthreads();

        // ---- conv1 + gate -> hT fp16 ----
        if (c1on) {
            #pragma unroll
            for (int j = 0; j < 27; j++) {
                int sp = sp0 + j * 3;           // 0..80
                if (sp < SPT * X) {
                    int s = sp / X, p = sp % X;
                    const float* ur = usf + s * 44 + p;
                    float u0 = ur[0], u1 = ur[1], u2 = ur[2], u3 = ur[3], u4 = ur[4];
                    float a = b1v;
                    a = fmaf(w1r[0], u0, a); a = fmaf(w1r[1], u1, a); a = fmaf(w1r[2], u2, a);
                    a = fmaf(w1r[3], u3, a); a = fmaf(w1r[4], u4, a);
                    a = fmaxf(a, 0.f);
                    if (c1c >= 24) {
                        float g = b1g;
                        g = fmaf(w1g[0], u0, g); g = fmaf(w1g[1], u1, g); g = fmaf(w1g[2], u2, g);
                        g = fmaf(w1g[3], u3, g); g = fmaf(w1g[4], u4, g);
                        a *= fmaxf(g, 0.f);
                    }
                    __half hv = __float2half(a);
                    __half* ht = hTh + s * HT_SAMP;
                    ht[(p + 2) * HTST + c1c] = hv;
                    if (p < 2)   ht[(p + 42) * HTST + c1c] = hv;
                    if (p >= 38) ht[(p - 38) * HTST + c1c] = hv;
                }
            }
        }
        __syncthreads();

        // ---- GEMM: 15 kt x 5 nt, A from hT, B from registers ----
        float acc[5][4];
        #pragma unroll
        for (int nt = 0; nt < 5; nt++)
            #pragma unroll
            for (int j = 0; j < 4; j++) acc[nt][j] = 0.f;

        #pragma unroll
        for (int kt = 0; kt < 15; kt++) {
            const int d   = kt / 3;
            const int ci0 = (kt % 3) * 16;
            uint32_t a0, a1, a2, a3;
            ldmatrix_x4(a0, a1, a2, a3, a_base + (uint32_t)((d * HTST + ci0) * 2));
            #pragma unroll
            for (int nt = 0; nt < 5; nt++)
                mma16816(acc[nt], a0, a1, a2, a3, bf[kt][nt][0], bf[kt][nt][1]);
        }

        // ---- epilogue: relu(acc+b2)*W3, in-thread + quad reduce ----
        {
            float sum0 = 0.f, sum1 = 0.f;
            #pragma unroll
            for (int nt = 0; nt < 5; nt++) {
                float4 w = bw[nt * 4 + (lane & 3)];
                sum0 += fmaxf(acc[nt][0] + w.x, 0.f) * w.z
                      + fmaxf(acc[nt][1] + w.y, 0.f) * w.w;
                sum1 += fmaxf(acc[nt][2] + w.x, 0.f) * w.z
                      + fmaxf(acc[nt][3] + w.y, 0.f) * w.w;
            }
            sum0 += __shfl_xor_sync(0xFFFFFFFF, sum0, 1);
            sum0 += __shfl_xor_sync(0xFFFFFFFF, sum0, 2);
            sum1 += __shfl_xor_sync(0xFFFFFFFF, sum1, 1);
            sum1 += __shfl_xor_sync(0xFFFFFFFF, sum1, 2);
            if ((lane & 3) == 0) {
                int r = lane >> 2;
                part[wid * 16 + r]     = sum0;
                part[wid * 16 + r + 8] = sum1;
            }
        }
        __syncthreads();

        // ---- final: stencil head + b3 + conv partial ----
        if (tid < SPT * X) {
            int s = tid / X, p = tid % X;
            const float* ur = usf + s * 44 + p;
            const float* cf = (const float*)(sm + SM_COEFF);
            float um2 = ur[0], um1 = ur[1], uc = ur[2], up1 = ur[3], up2 = ur[4];
            float o = cf[0];
            o = fmaf(cf[1],  um2,       o);
            o = fmaf(cf[2],  um1,       o);
            o = fmaf(cf[3],  uc,        o);
            o = fmaf(cf[4],  up1,       o);
            o = fmaf(cf[5],  up2,       o);
            o = fmaf(cf[6],  um2 * um2, o);
            o = fmaf(cf[7],  um1 * um1, o);
            o = fmaf(cf[8],  uc  * uc,  o);
            o = fmaf(cf[9],  up1 * up1, o);
            o = fmaf(cf[10], up2 * up2, o);
            o = fmaf(cf[11], um2 * um1, o);
            o = fmaf(cf[12], um1 * uc,  o);
            o = fmaf(cf[13], uc  * up1, o);
            o = fmaf(cf[14], up1 * up2, o);
            o = fmaf(cf[15], um2 * uc,  o);
            o = fmaf(cf[16], um1 * up1, o);
            o = fmaf(cf[17], uc  * up2, o);
            o += ((float*)(sm + SM_B3))[0];
            o += part[tid];
            out[gbase + tid] = o;
        }
        __syncthreads();
    }
}

extern "C" void kernel_launch(void* const* d_in, const int* in_sizes, int n_in,
                              void* d_out, int out_size)
{
    // inputs: 0:t 1:u 2:coeff 3:W1 4:b1 5:W2 6:b2 7:W3 8:b3
    const float* u     = (const float*)d_in[1];
    const float* coeff = (const float*)d_in[2];
    const float* W1    = (const float*)d_in[3];
    const float* b1    = (const float*)d_in[4];
    const float* W2    = (const float*)d_in[5];
    const float* b2    = (const float*)d_in[6];
    const float* W3    = (const float*)d_in[7];
    const float* b3    = (const float*)d_in[8];
    float* out = (float*)d_out;

    cudaFuncSetAttribute(l96_flip_kernel, cudaFuncAttributeMaxDynamicSharedMemorySize, SM_TOTAL);
    l96_flip_kernel<<<GRID, NT, SM_TOTAL>>>(u, coeff, W1, b1, W2, b2, W3, b3, out);
}